// round 11
// baseline (speedup 1.0000x reference)
#include <cuda_runtime.h>
#include <cstdint>

#define B_DIM 2048
#define T_DIM 32
#define K_DIM 1024
#define D_DIM 256

#define BM 128
#define BN 128
#define BK 16

// packed (hi,lo) float2 smem addressing: ad2 = 148*k + row + 8*((k>>3)&1).
// 64-bit fragment LDS banks: (8*lr4 + 2*lq) mod 32 -> distinct per phase.
// 64-bit STS banks: (8e + 2*lr + 16h) mod 32 -> distinct per phase.
#define KADDR2(k, row) ((k) * 148 + (((k) >> 3) & 1) * 8 + (row))
#define ARR2 2364            // > KADDR2(15,135)=2363 float2 elements

__device__ float g_csq[T_DIM * K_DIM];

// ---------------------------------------------------------------------------
// Kernel 1: c_sq[t,k] = sum_d codebook[t,k,d]^2.  One warp per code.
// ---------------------------------------------------------------------------
__global__ void csq_kernel(const float* __restrict__ codebook) {
    int gw   = blockIdx.x * (blockDim.x >> 5) + (threadIdx.x >> 5);
    int lane = threadIdx.x & 31;
    if (gw >= T_DIM * K_DIM) return;
    const float4* p = reinterpret_cast<const float4*>(codebook + (size_t)gw * D_DIM);
    float4 v0 = p[lane];
    float4 v1 = p[lane + 32];
    float s = v0.x*v0.x + v0.y*v0.y + v0.z*v0.z + v0.w*v0.w
            + v1.x*v1.x + v1.y*v1.y + v1.z*v1.z + v1.w*v1.w;
    #pragma unroll
    for (int o = 16; o > 0; o >>= 1) s += __shfl_xor_sync(0xffffffffu, s, o);
    if (lane == 0) g_csq[gw] = s;
}

// m16n8k8 TF32 warp MMA (sm_80+ PTX — valid on base sm_100 target)
__device__ __forceinline__ void mma_tf32(float* c, const uint32_t* a,
                                         const uint32_t* b) {
    asm volatile(
        "mma.sync.aligned.m16n8k8.row.col.f32.tf32.tf32.f32 "
        "{%0,%1,%2,%3}, {%4,%5,%6,%7}, {%8,%9}, {%0,%1,%2,%3};"
        : "+f"(c[0]), "+f"(c[1]), "+f"(c[2]), "+f"(c[3])
        : "r"(a[0]), "r"(a[1]), "r"(a[2]), "r"(a[3]), "r"(b[0]), "r"(b[1]));
}

// ---------------------------------------------------------------------------
// Kernel 2: fused GEMM (3xTF32 split via mma.sync) + argmin + gather.
// CTA = 256 thr (8 warps, 2x4), one t, 128 input rows; loops 8 N-tiles.
// Hi/lo split once at staging, PACKED as float2 -> one LDS.64 fetches both
// halves of an element. Inner loop: 24 LDS.64 per 48 HMMA per kf.
// ---------------------------------------------------------------------------
__global__ __launch_bounds__(256, 2) void vsq_mma_kernel(
    const float* __restrict__ input,
    const float* __restrict__ codebook,
    float* __restrict__ out)
{
    extern __shared__ float sm[];
    float* csq_s = sm;                                        // 1024 floats
    unsigned long long* minpack =
        reinterpret_cast<unsigned long long*>(sm + 1024);     // 128 ull
    float2* bufs2 = reinterpret_cast<float2*>(sm + 1280);     // 2 x 2 x ARR2

    const int t     = blockIdx.y;
    const int mBase = blockIdx.x * BM;
    const int tid   = threadIdx.x;
    const int lane  = tid & 31;
    const int wid   = tid >> 5;
    const int wm    = wid >> 2;        // 0..1  (m half)
    const int wn    = wid & 3;         // 0..3  (n quarter)
    const int lq    = lane >> 2;       // 0..7
    const int lr4   = lane & 3;        // 0..3

    // loader mapping: one row, 8 contiguous k per thread (BK=16)
    const int lr = tid >> 1;
    const int lh = tid & 1;            // k half (0: k0-7, 1: k8-15)

    for (int i = tid; i < K_DIM; i += 256) csq_s[i] = g_csq[t * K_DIM + i];
    if (tid < BM) minpack[tid] = 0xFFFFFFFFFFFFFFFFull;
    __syncthreads();

    const size_t ARowStride = (size_t)T_DIM * D_DIM;
    const float* Abase = input    + ((size_t)mBase * T_DIM + t) * D_DIM;
    const float* Cb    = codebook + (size_t)t * K_DIM * D_DIM;

    // staging base address for this thread (k = 8*lh + e, row = lr)
    const int stBase = 148 * 8 * lh + 8 * lh + lr;

    float rmin[8];
    int   ridx[8];
    #pragma unroll
    for (int i = 0; i < 8; i++) { rmin[i] = 3.4e38f; ridx[i] = 0; }

    int buf = 0;
    for (int nTile = 0; nTile < K_DIM / BN; nTile++) {
        const int nBase = nTile * BN;

        float acc[4][4][4];
        #pragma unroll
        for (int mf = 0; mf < 4; mf++)
            #pragma unroll
            for (int nf = 0; nf < 4; nf++)
                #pragma unroll
                for (int r = 0; r < 4; r++) acc[mf][nf][r] = 0.0f;

        const float* Ap = Abase + (size_t)lr * ARowStride + lh * 8;
        const float* Bp = Cb + (size_t)(nBase + lr) * D_DIM + lh * 8;

        float va[8], vb[8];
        #pragma unroll
        for (int i = 0; i < 2; i++) {
            *reinterpret_cast<float4*>(va + i * 4) =
                *reinterpret_cast<const float4*>(Ap + i * 4);
            *reinterpret_cast<float4*>(vb + i * 4) =
                *reinterpret_cast<const float4*>(Bp + i * 4);
        }
        {
            float2* Apk = bufs2 + buf * (2 * ARR2);
            float2* Bpk = Apk + ARR2;
            #pragma unroll
            for (int e = 0; e < 8; e++) {
                const int ad = stBase + 148 * e;
                float ha = __uint_as_float(__float_as_uint(va[e]) & 0xFFFFE000u);
                float hb = __uint_as_float(__float_as_uint(vb[e]) & 0xFFFFE000u);
                Apk[ad] = make_float2(ha, va[e] - ha);
                Bpk[ad] = make_float2(hb, vb[e] - hb);
            }
        }
        __syncthreads();

        for (int kt = 0; kt < D_DIM / BK; kt++) {
            const bool more = (kt + 1) < (D_DIM / BK);
            if (more) {
                Ap += BK; Bp += BK;
                #pragma unroll
                for (int i = 0; i < 2; i++) {
                    *reinterpret_cast<float4*>(va + i * 4) =
                        *reinterpret_cast<const float4*>(Ap + i * 4);
                    *reinterpret_cast<float4*>(vb + i * 4) =
                        *reinterpret_cast<const float4*>(Bp + i * 4);
                }
            }

            const float2* Apk = bufs2 + buf * (2 * ARR2);
            const float2* Bpk = Apk + ARR2;

            #pragma unroll
            for (int kf = 0; kf < 2; kf++) {
                uint32_t bh[4][2], bl[4][2];
                #pragma unroll
                for (int nf = 0; nf < 4; nf++)
                    #pragma unroll
                    for (int j = 0; j < 2; j++) {
                        const int ad = KADDR2(kf * 8 + lr4 + j * 4,
                                              wn * 32 + nf * 8 + lq);
                        float2 b = Bpk[ad];
                        bh[nf][j] = __float_as_uint(b.x);
                        bl[nf][j] = __float_as_uint(b.y);
                    }
                #pragma unroll
                for (int mf = 0; mf < 4; mf++) {
                    uint32_t ah[4], al[4];
                    #pragma unroll
                    for (int j = 0; j < 4; j++) {
                        const int ad = KADDR2(kf * 8 + lr4 + (j >> 1) * 4,
                                              wm * 64 + mf * 16 + lq + (j & 1) * 8);
                        float2 a = Apk[ad];
                        ah[j] = __float_as_uint(a.x);
                        al[j] = __float_as_uint(a.y);
                    }
                    #pragma unroll
                    for (int nf = 0; nf < 4; nf++) {
                        mma_tf32(acc[mf][nf], al, bh[nf]);  // small terms first
                        mma_tf32(acc[mf][nf], ah, bl[nf]);
                        mma_tf32(acc[mf][nf], ah, bh[nf]);
                    }
                }
            }

            if (more) {
                const int nb = buf ^ 1;
                float2* Apkn = bufs2 + nb * (2 * ARR2);
                float2* Bpkn = Apkn + ARR2;
                #pragma unroll
                for (int e = 0; e < 8; e++) {
                    const int ad = stBase + 148 * e;
                    float ha = __uint_as_float(__float_as_uint(va[e]) & 0xFFFFE000u);
                    float hb = __uint_as_float(__float_as_uint(vb[e]) & 0xFFFFE000u);
                    Apkn[ad] = make_float2(ha, va[e] - ha);
                    Bpkn[ad] = make_float2(hb, vb[e] - hb);
                }
                buf = nb;
            }
            __syncthreads();
        }

        // fold into running argmin (per-thread n strictly ascending ->
        // '<' keeps first occurrence, matching jnp.argmin)
        #pragma unroll
        for (int mf = 0; mf < 4; mf++)
            #pragma unroll
            for (int half = 0; half < 2; half++) {
                const int i = mf * 2 + half;
                #pragma unroll
                for (int nf = 0; nf < 4; nf++) {
                    const int n0 = nBase + wn * 32 + nf * 8 + lr4 * 2;
                    const float d0 = fmaf(-2.0f, acc[mf][nf][half * 2 + 0], csq_s[n0]);
                    const float d1 = fmaf(-2.0f, acc[mf][nf][half * 2 + 1], csq_s[n0 + 1]);
                    if (d0 < rmin[i]) { rmin[i] = d0; ridx[i] = n0; }
                    if (d1 < rmin[i]) { rmin[i] = d1; ridx[i] = n0 + 1; }
                }
            }
    }

    // reduce across the 4 lanes sharing each row (xor 1,2 within quad),
    // then global combine across the 4 n-warps via packed atomicMin.
    #pragma unroll
    for (int i = 0; i < 8; i++) {
        float d  = rmin[i];
        int   ix = ridx[i];
        #pragma unroll
        for (int o = 1; o <= 2; o <<= 1) {
            float od = __shfl_xor_sync(0xffffffffu, d, o);
            int   oi = __shfl_xor_sync(0xffffffffu, ix, o);
            if (od < d || (od == d && oi < ix)) { d = od; ix = oi; }
        }
        if (lr4 == 0) {
            const int row = wm * 64 + (i >> 1) * 16 + (i & 1) * 8 + lq;
            uint32_t db = __float_as_uint(d);
            uint32_t key = (db & 0x80000000u) ? ~db : (db | 0x80000000u);
            unsigned long long pk =
                ((unsigned long long)key << 32) | (uint32_t)ix;
            atomicMin(&minpack[row], pk);
        }
    }
    __syncthreads();

    // cooperative gather: embed[b,t,:] = codebook[t, argmin, :]
    for (int q = tid; q < BM * (D_DIM / 4); q += 256) {
        const int r  = q >> 6;
        const int c  = q & 63;
        const int bi = (int)(uint32_t)(minpack[r] & 0xFFFFFFFFull);
        float4 v = *reinterpret_cast<const float4*>(Cb + (size_t)bi * D_DIM + c * 4);
        *reinterpret_cast<float4*>(
            out + ((size_t)(mBase + r) * T_DIM + t) * D_DIM + c * 4) = v;
    }
    // idxes (float, concatenated after embed in the float32 output)
    if (tid < BM) {
        out[(size_t)B_DIM * T_DIM * D_DIM + (size_t)(mBase + tid) * T_DIM + t]
            = (float)(uint32_t)(minpack[tid] & 0xFFFFFFFFull);
    }
}

// ---------------------------------------------------------------------------
static const uint32_t SMEM_BYTES = 1280u * 4u + 2u * 2u * ARR2 * 8u;  // 80768

extern "C" void kernel_launch(void* const* d_in, const int* in_sizes, int n_in,
                              void* d_out, int out_size) {
    const float* input    = (const float*)d_in[0];
    const float* codebook = (const float*)d_in[1];
    float* out = (float*)d_out;

    cudaFuncSetAttribute(vsq_mma_kernel,
                         cudaFuncAttributeMaxDynamicSharedMemorySize, SMEM_BYTES);

    csq_kernel<<<(T_DIM * K_DIM) / 8, 256>>>(codebook);

    dim3 grid(B_DIM / BM, T_DIM);
    vsq_mma_kernel<<<grid, 256, SMEM_BYTES>>>(input, codebook, out);
}

// round 12
// speedup vs baseline: 1.2415x; 1.2415x over previous
#include <cuda_runtime.h>
#include <cstdint>

#define B_DIM 2048
#define T_DIM 32
#define K_DIM 1024
#define D_DIM 256

#define BM 128
#define BN 128
#define BK 16

// smem addressing for split tiles: [k][row], row stride 136 (==8 mod 32 ->
// fragment LDS banks 8*lr4+lq all-distinct), plus 16-float offset for k>=8 so
// the two k-halves written by one STS instruction hit disjoint bank groups.
#define KADDR(k, row) ((k) * 136 + (((k) >> 3) & 1) * 16 + (row))
#define ARR_STRIDE 2192            // > KADDR(15,135)=2191, 16B-aligned*4

__device__ float g_csq[T_DIM * K_DIM];

// ---------------------------------------------------------------------------
// Kernel 1: c_sq[t,k] = sum_d codebook[t,k,d]^2.  One warp per code.
// ---------------------------------------------------------------------------
__global__ void csq_kernel(const float* __restrict__ codebook) {
    int gw   = blockIdx.x * (blockDim.x >> 5) + (threadIdx.x >> 5);
    int lane = threadIdx.x & 31;
    if (gw >= T_DIM * K_DIM) return;
    const float4* p = reinterpret_cast<const float4*>(codebook + (size_t)gw * D_DIM);
    float4 v0 = p[lane];
    float4 v1 = p[lane + 32];
    float s = v0.x*v0.x + v0.y*v0.y + v0.z*v0.z + v0.w*v0.w
            + v1.x*v1.x + v1.y*v1.y + v1.z*v1.z + v1.w*v1.w;
    #pragma unroll
    for (int o = 16; o > 0; o >>= 1) s += __shfl_xor_sync(0xffffffffu, s, o);
    if (lane == 0) g_csq[gw] = s;
}

// m16n8k8 TF32 warp MMA (sm_80+ PTX — valid on base sm_100 target)
__device__ __forceinline__ void mma_tf32(float* c, const uint32_t* a,
                                         const uint32_t* b) {
    asm volatile(
        "mma.sync.aligned.m16n8k8.row.col.f32.tf32.tf32.f32 "
        "{%0,%1,%2,%3}, {%4,%5,%6,%7}, {%8,%9}, {%0,%1,%2,%3};"
        : "+f"(c[0]), "+f"(c[1]), "+f"(c[2]), "+f"(c[3])
        : "r"(a[0]), "r"(a[1]), "r"(a[2]), "r"(a[3]), "r"(b[0]), "r"(b[1]));
}

// ---------------------------------------------------------------------------
// Kernel 2: fused GEMM (3xTF32 split via mma.sync) + argmin + gather.
// CTA = 256 thr (8 warps, 2x4), one t, 128 input rows; loops 8 N-tiles.
// Hi/lo split once at staging (round-10 layout). Inner loop SOFTWARE-
// PIPELINED: two rotating A-fragment buffers so every fragment LDS issues
// >=12 HMMA before first use.
// ---------------------------------------------------------------------------
__global__ __launch_bounds__(256, 2) void vsq_mma_kernel(
    const float* __restrict__ input,
    const float* __restrict__ codebook,
    float* __restrict__ out)
{
    extern __shared__ float sm[];
    float* csq_s = sm;                                        // 1024 floats
    unsigned long long* minpack =
        reinterpret_cast<unsigned long long*>(sm + 1024);     // 128 ull
    float* bufs = sm + 1280;                                  // 2 x 4 x ARR_STRIDE

    const int t     = blockIdx.y;
    const int mBase = blockIdx.x * BM;
    const int tid   = threadIdx.x;
    const int lane  = tid & 31;
    const int wid   = tid >> 5;
    const int wm    = wid >> 2;        // 0..1  (m half)
    const int wn    = wid & 3;         // 0..3  (n quarter)
    const int lq    = lane >> 2;       // 0..7
    const int lr4   = lane & 3;        // 0..3

    // loader mapping: one row, 8 contiguous k per thread (BK=16)
    const int lr = tid >> 1;
    const int lc = (tid & 1) * 8;

    for (int i = tid; i < K_DIM; i += 256) csq_s[i] = g_csq[t * K_DIM + i];
    if (tid < BM) minpack[tid] = 0xFFFFFFFFFFFFFFFFull;
    __syncthreads();

    const size_t ARowStride = (size_t)T_DIM * D_DIM;
    const float* Abase = input    + ((size_t)mBase * T_DIM + t) * D_DIM;
    const float* Cb    = codebook + (size_t)t * K_DIM * D_DIM;

    float rmin[8];
    int   ridx[8];
    #pragma unroll
    for (int i = 0; i < 8; i++) { rmin[i] = 3.4e38f; ridx[i] = 0; }

#define LOAD_B(kf)                                                        \
    _Pragma("unroll")                                                     \
    for (int nf = 0; nf < 4; nf++) {                                      \
        _Pragma("unroll")                                                 \
        for (int j = 0; j < 2; j++) {                                     \
            const int ad = KADDR((kf) * 8 + lr4 + j * 4,                  \
                                 wn * 32 + nf * 8 + lq);                  \
            bh[nf][j] = __float_as_uint(Bh[ad]);                          \
            bl[nf][j] = __float_as_uint(Bl[ad]);                          \
        }                                                                 \
    }

#define LOAD_A(AH, AL, kf, mf)                                            \
    _Pragma("unroll")                                                     \
    for (int j = 0; j < 4; j++) {                                         \
        const int ad = KADDR((kf) * 8 + lr4 + (j >> 1) * 4,               \
                             wm * 64 + (mf) * 16 + lq + (j & 1) * 8);     \
        AH[j] = __float_as_uint(Ah[ad]);                                  \
        AL[j] = __float_as_uint(Al[ad]);                                  \
    }

#define MMA_STAGE(mf, AH, AL)                                             \
    _Pragma("unroll")                                                     \
    for (int nf = 0; nf < 4; nf++) {                                      \
        mma_tf32(acc[mf][nf], AL, bh[nf]);  /* small terms first */       \
        mma_tf32(acc[mf][nf], AH, bl[nf]);                                \
        mma_tf32(acc[mf][nf], AH, bh[nf]);                                \
    }

    int buf = 0;
    for (int nTile = 0; nTile < K_DIM / BN; nTile++) {
        const int nBase = nTile * BN;

        float acc[4][4][4];
        #pragma unroll
        for (int mf = 0; mf < 4; mf++)
            #pragma unroll
            for (int nf = 0; nf < 4; nf++)
                #pragma unroll
                for (int r = 0; r < 4; r++) acc[mf][nf][r] = 0.0f;

        const float* Ap = Abase + (size_t)lr * ARowStride + lc;
        const float* Bp = Cb + (size_t)(nBase + lr) * D_DIM + lc;

        float va[8], vb[8];
        #pragma unroll
        for (int i = 0; i < 2; i++) {
            *reinterpret_cast<float4*>(va + i * 4) =
                *reinterpret_cast<const float4*>(Ap + i * 4);
            *reinterpret_cast<float4*>(vb + i * 4) =
                *reinterpret_cast<const float4*>(Bp + i * 4);
        }
        {
            float* Ahs = bufs + buf * 4 * ARR_STRIDE;
            float* Als = Ahs + ARR_STRIDE;
            float* Bhs = Als + ARR_STRIDE;
            float* Bls = Bhs + ARR_STRIDE;
            #pragma unroll
            for (int e = 0; e < 8; e++) {
                const int ad = KADDR(lc + e, lr);
                float ha = __uint_as_float(__float_as_uint(va[e]) & 0xFFFFE000u);
                float hb = __uint_as_float(__float_as_uint(vb[e]) & 0xFFFFE000u);
                Ahs[ad] = ha; Als[ad] = va[e] - ha;
                Bhs[ad] = hb; Bls[ad] = vb[e] - hb;
            }
        }
        __syncthreads();

        for (int kt = 0; kt < D_DIM / BK; kt++) {
            const bool more = (kt + 1) < (D_DIM / BK);
            if (more) {
                Ap += BK; Bp += BK;
                #pragma unroll
                for (int i = 0; i < 2; i++) {
                    *reinterpret_cast<float4*>(va + i * 4) =
                        *reinterpret_cast<const float4*>(Ap + i * 4);
                    *reinterpret_cast<float4*>(vb + i * 4) =
                        *reinterpret_cast<const float4*>(Bp + i * 4);
                }
            }

            const float* Ah = bufs + buf * 4 * ARR_STRIDE;
            const float* Al = Ah + ARR_STRIDE;
            const float* Bh = Al + ARR_STRIDE;
            const float* Bl = Bh + ARR_STRIDE;

            uint32_t bh[4][2], bl[4][2];
            uint32_t a0h[4], a0l[4], a1h[4], a1l[4];

            #pragma unroll
            for (int kf = 0; kf < 2; kf++) {
                LOAD_B(kf);
                LOAD_A(a0h, a0l, kf, 0);
                LOAD_A(a1h, a1l, kf, 1);
                MMA_STAGE(0, a0h, a0l);
                LOAD_A(a0h, a0l, kf, 2);
                MMA_STAGE(1, a1h, a1l);
                LOAD_A(a1h, a1l, kf, 3);
                MMA_STAGE(2, a0h, a0l);
                MMA_STAGE(3, a1h, a1l);
            }

            if (more) {
                const int nb = buf ^ 1;
                float* Ahn = bufs + nb * 4 * ARR_STRIDE;
                float* Aln = Ahn + ARR_STRIDE;
                float* Bhn = Aln + ARR_STRIDE;
                float* Bln = Bhn + ARR_STRIDE;
                #pragma unroll
                for (int e = 0; e < 8; e++) {
                    const int ad = KADDR(lc + e, lr);
                    float ha = __uint_as_float(__float_as_uint(va[e]) & 0xFFFFE000u);
                    float hb = __uint_as_float(__float_as_uint(vb[e]) & 0xFFFFE000u);
                    Ahn[ad] = ha; Aln[ad] = va[e] - ha;
                    Bhn[ad] = hb; Bln[ad] = vb[e] - hb;
                }
                buf = nb;
            }
            __syncthreads();
        }

        // fold into running argmin (per-thread n strictly ascending ->
        // '<' keeps first occurrence, matching jnp.argmin)
        #pragma unroll
        for (int mf = 0; mf < 4; mf++)
            #pragma unroll
            for (int half = 0; half < 2; half++) {
                const int i = mf * 2 + half;
                #pragma unroll
                for (int nf = 0; nf < 4; nf++) {
                    const int n0 = nBase + wn * 32 + nf * 8 + lr4 * 2;
                    const float d0 = fmaf(-2.0f, acc[mf][nf][half * 2 + 0], csq_s[n0]);
                    const float d1 = fmaf(-2.0f, acc[mf][nf][half * 2 + 1], csq_s[n0 + 1]);
                    if (d0 < rmin[i]) { rmin[i] = d0; ridx[i] = n0; }
                    if (d1 < rmin[i]) { rmin[i] = d1; ridx[i] = n0 + 1; }
                }
            }
    }

    // reduce across the 4 lanes sharing each row (xor 1,2 within quad),
    // then global combine across the 4 n-warps via packed atomicMin.
    #pragma unroll
    for (int i = 0; i < 8; i++) {
        float d  = rmin[i];
        int   ix = ridx[i];
        #pragma unroll
        for (int o = 1; o <= 2; o <<= 1) {
            float od = __shfl_xor_sync(0xffffffffu, d, o);
            int   oi = __shfl_xor_sync(0xffffffffu, ix, o);
            if (od < d || (od == d && oi < ix)) { d = od; ix = oi; }
        }
        if (lr4 == 0) {
            const int row = wm * 64 + (i >> 1) * 16 + (i & 1) * 8 + lq;
            uint32_t db = __float_as_uint(d);
            uint32_t key = (db & 0x80000000u) ? ~db : (db | 0x80000000u);
            unsigned long long pk =
                ((unsigned long long)key << 32) | (uint32_t)ix;
            atomicMin(&minpack[row], pk);
        }
    }
    __syncthreads();

    // cooperative gather: embed[b,t,:] = codebook[t, argmin, :]
    for (int q = tid; q < BM * (D_DIM / 4); q += 256) {
        const int r  = q >> 6;
        const int c  = q & 63;
        const int bi = (int)(uint32_t)(minpack[r] & 0xFFFFFFFFull);
        float4 v = *reinterpret_cast<const float4*>(Cb + (size_t)bi * D_DIM + c * 4);
        *reinterpret_cast<float4*>(
            out + ((size_t)(mBase + r) * T_DIM + t) * D_DIM + c * 4) = v;
    }
    // idxes (float, concatenated after embed in the float32 output)
    if (tid < BM) {
        out[(size_t)B_DIM * T_DIM * D_DIM + (size_t)(mBase + tid) * T_DIM + t]
            = (float)(uint32_t)(minpack[tid] & 0xFFFFFFFFull);
    }
}

// ---------------------------------------------------------------------------
static const uint32_t SMEM_BYTES = (1280u + 2u * 4u * ARR_STRIDE) * 4u;  // 75264

extern "C" void kernel_launch(void* const* d_in, const int* in_sizes, int n_in,
                              void* d_out, int out_size) {
    const float* input    = (const float*)d_in[0];
    const float* codebook = (const float*)d_in[1];
    float* out = (float*)d_out;

    cudaFuncSetAttribute(vsq_mma_kernel,
                         cudaFuncAttributeMaxDynamicSharedMemorySize, SMEM_BYTES);

    csq_kernel<<<(T_DIM * K_DIM) / 8, 256>>>(codebook);

    dim3 grid(B_DIM / BM, T_DIM);
    vsq_mma_kernel<<<grid, 256, SMEM_BYTES>>>(input, codebook, out);
}

// round 15
// speedup vs baseline: 1.8509x; 1.4908x over previous
// VSQ fused GEMM+argmin — fp16 3x-split mma.sync variant (resubmit r13, renamed)
#include <cuda_runtime.h>
#include <cuda_fp16.h>
#include <cstdint>

#define B_DIM 2048
#define T_DIM 32
#define K_DIM 1024
#define D_DIM 256

#define BM 128
#define BN 128
#define BK 16

// half2 smem addressing: [k2][row], k2 = k/2 (0..7), stride 136 (==8 mod 32),
// plus 16-word offset for k2>=4 so paired STS halves hit disjoint bank groups.
// STS banks: (16*lh + 8*e2 + lr) mod 32 distinct; fragment LDS banks
// (8*lr4 + lq) / (+16) distinct. Conflict-free by construction.
#define KADDRH(k2, row) ((k2) * 136 + (((k2) >> 2) & 1) * 16 + (row))
#define ARR_H 1104          // > KADDRH(7,135)=1103 (32-bit words)

__device__ float g_csq_norms[T_DIM * K_DIM];

// ---------------------------------------------------------------------------
// Kernel 1: c_sq[t,k] = sum_d codebook[t,k,d]^2.  One warp per code.
// ---------------------------------------------------------------------------
__global__ void csq_norm_kernel(const float* __restrict__ codebook) {
    int gw   = blockIdx.x * (blockDim.x >> 5) + (threadIdx.x >> 5);
    int lane = threadIdx.x & 31;
    if (gw >= T_DIM * K_DIM) return;
    const float4* p = reinterpret_cast<const float4*>(codebook + (size_t)gw * D_DIM);
    float4 v0 = p[lane];
    float4 v1 = p[lane + 32];
    float s = v0.x*v0.x + v0.y*v0.y + v0.z*v0.z + v0.w*v0.w
            + v1.x*v1.x + v1.y*v1.y + v1.z*v1.z + v1.w*v1.w;
    #pragma unroll
    for (int o = 16; o > 0; o >>= 1) s += __shfl_xor_sync(0xffffffffu, s, o);
    if (lane == 0) g_csq_norms[gw] = s;
}

// pack two f32 -> f16x2 (x0 in low half), RN
__device__ __forceinline__ uint32_t pack_h2(float x0, float x1) {
    uint32_t r;
    asm("cvt.rn.f16x2.f32 %0, %1, %2;" : "=r"(r) : "f"(x1), "f"(x0));
    return r;
}

// m16n8k16 FP16 warp MMA, fp32 accumulate (sm_80+ PTX, valid on base sm_100)
__device__ __forceinline__ void mma_f16(float* c, const uint32_t* a,
                                        const uint32_t* b) {
    asm volatile(
        "mma.sync.aligned.m16n8k16.row.col.f32.f16.f16.f32 "
        "{%0,%1,%2,%3}, {%4,%5,%6,%7}, {%8,%9}, {%0,%1,%2,%3};"
        : "+f"(c[0]), "+f"(c[1]), "+f"(c[2]), "+f"(c[3])
        : "r"(a[0]), "r"(a[1]), "r"(a[2]), "r"(a[3]), "r"(b[0]), "r"(b[1]));
}

// ---------------------------------------------------------------------------
// Kernel 2: fused GEMM (3xFP16 split via mma.sync.m16n8k16) + argmin + gather.
// CTA = 256 thr (8 warps, 2x4), one t, 128 input rows; loops 8 N-tiles.
// fp32 split into fp16 hi/lo ONCE at staging (same 11-bit hi mantissa as the
// proven 3xTF32 path -> identical error structure). k16 per MMA halves the
// HMMA instruction count vs tf32 k8.
// ---------------------------------------------------------------------------
__global__ __launch_bounds__(256, 2) void vsq_f16_kernel(
    const float* __restrict__ input,
    const float* __restrict__ codebook,
    float* __restrict__ out)
{
    extern __shared__ float sm[];
    float* csq_s = sm;                                        // 1024 floats
    unsigned long long* minpack =
        reinterpret_cast<unsigned long long*>(sm + 1024);     // 128 ull
    uint32_t* bufs = reinterpret_cast<uint32_t*>(sm + 1280);  // 2 x 4 x ARR_H

    const int t     = blockIdx.y;
    const int mBase = blockIdx.x * BM;
    const int tid   = threadIdx.x;
    const int lane  = tid & 31;
    const int wid   = tid >> 5;
    const int wm    = wid >> 2;        // 0..1  (m half)
    const int wn    = wid & 3;         // 0..3  (n quarter)
    const int lq    = lane >> 2;       // 0..7
    const int lr4   = lane & 3;        // 0..3

    // loader mapping: one row, 8 contiguous k per thread (BK=16)
    const int lr = tid >> 1;
    const int lh = tid & 1;            // k half (0: k0-7, 1: k8-15)

    for (int i = tid; i < K_DIM; i += 256) csq_s[i] = g_csq_norms[t * K_DIM + i];
    if (tid < BM) minpack[tid] = 0xFFFFFFFFFFFFFFFFull;
    __syncthreads();

    const size_t ARowStride = (size_t)T_DIM * D_DIM;
    const float* Abase = input    + ((size_t)mBase * T_DIM + t) * D_DIM;
    const float* Cb    = codebook + (size_t)t * K_DIM * D_DIM;

    float rmin[8];
    int   ridx[8];
    #pragma unroll
    for (int i = 0; i < 8; i++) { rmin[i] = 3.4e38f; ridx[i] = 0; }

// split va[8]/vb[8] (k = 8*lh..8*lh+7 of row lr) into fp16 hi/lo pairs
#define STAGE_SPLIT(AH, AL, BH, BL)                                       \
    _Pragma("unroll")                                                     \
    for (int e2 = 0; e2 < 4; e2++) {                                      \
        const int ad = KADDRH(4 * lh + e2, lr);                           \
        float x0 = va[2 * e2], x1 = va[2 * e2 + 1];                       \
        uint32_t h = pack_h2(x0, x1);                                     \
        float2 hf = __half22float2(*reinterpret_cast<__half2*>(&h));      \
        (AH)[ad] = h;                                                     \
        (AL)[ad] = pack_h2(x0 - hf.x, x1 - hf.y);                         \
        float y0 = vb[2 * e2], y1 = vb[2 * e2 + 1];                       \
        uint32_t g = pack_h2(y0, y1);                                     \
        float2 gf = __half22float2(*reinterpret_cast<__half2*>(&g));      \
        (BH)[ad] = g;                                                     \
        (BL)[ad] = pack_h2(y0 - gf.x, y1 - gf.y);                         \
    }

    int buf = 0;
    for (int nTile = 0; nTile < K_DIM / BN; nTile++) {
        const int nBase = nTile * BN;

        float acc[4][4][4];
        #pragma unroll
        for (int mf = 0; mf < 4; mf++)
            #pragma unroll
            for (int nf = 0; nf < 4; nf++)
                #pragma unroll
                for (int r = 0; r < 4; r++) acc[mf][nf][r] = 0.0f;

        const float* Ap = Abase + (size_t)lr * ARowStride + lh * 8;
        const float* Bp = Cb + (size_t)(nBase + lr) * D_DIM + lh * 8;

        float va[8], vb[8];
        #pragma unroll
        for (int i = 0; i < 2; i++) {
            *reinterpret_cast<float4*>(va + i * 4) =
                *reinterpret_cast<const float4*>(Ap + i * 4);
            *reinterpret_cast<float4*>(vb + i * 4) =
                *reinterpret_cast<const float4*>(Bp + i * 4);
        }
        {
            uint32_t* Ah = bufs + buf * 4 * ARR_H;
            uint32_t* Al = Ah + ARR_H;
            uint32_t* Bh = Al + ARR_H;
            uint32_t* Bl = Bh + ARR_H;
            STAGE_SPLIT(Ah, Al, Bh, Bl);
        }
        __syncthreads();

        for (int kt = 0; kt < D_DIM / BK; kt++) {
            const bool more = (kt + 1) < (D_DIM / BK);
            if (more) {
                Ap += BK; Bp += BK;
                #pragma unroll
                for (int i = 0; i < 2; i++) {
                    *reinterpret_cast<float4*>(va + i * 4) =
                        *reinterpret_cast<const float4*>(Ap + i * 4);
                    *reinterpret_cast<float4*>(vb + i * 4) =
                        *reinterpret_cast<const float4*>(Bp + i * 4);
                }
            }

            const uint32_t* Ah = bufs + buf * 4 * ARR_H;
            const uint32_t* Al = Ah + ARR_H;
            const uint32_t* Bh = Al + ARR_H;
            const uint32_t* Bl = Bh + ARR_H;

            // B fragments: b[j] = {k=2*(lr4+4j), 2*(lr4+4j)+1} x col lq
            uint32_t bh[4][2], bl[4][2];
            #pragma unroll
            for (int nf = 0; nf < 4; nf++)
                #pragma unroll
                for (int j = 0; j < 2; j++) {
                    const int ad = KADDRH(lr4 + j * 4, wn * 32 + nf * 8 + lq);
                    bh[nf][j] = Bh[ad];
                    bl[nf][j] = Bl[ad];
                }

            #pragma unroll
            for (int mf = 0; mf < 4; mf++) {
                uint32_t ah[4], al[4];
                #pragma unroll
                for (int j = 0; j < 4; j++) {
                    const int ad = KADDRH(lr4 + (j >> 1) * 4,
                                          wm * 64 + mf * 16 + lq + (j & 1) * 8);
                    ah[j] = Ah[ad];
                    al[j] = Al[ad];
                }
                #pragma unroll
                for (int nf = 0; nf < 4; nf++) {
                    mma_f16(acc[mf][nf], al, bh[nf]);  // small terms first
                    mma_f16(acc[mf][nf], ah, bl[nf]);
                    mma_f16(acc[mf][nf], ah, bh[nf]);
                }
            }

            if (more) {
                const int nb = buf ^ 1;
                uint32_t* Ahn = bufs + nb * 4 * ARR_H;
                uint32_t* Aln = Ahn + ARR_H;
                uint32_t* Bhn = Aln + ARR_H;
                uint32_t* Bln = Bhn + ARR_H;
                STAGE_SPLIT(Ahn, Aln, Bhn, Bln);
                buf = nb;
            }
            __syncthreads();
        }

        // fold into running argmin (per-thread n strictly ascending ->
        // '<' keeps first occurrence, matching jnp.argmin)
        #pragma unroll
        for (int mf = 0; mf < 4; mf++)
            #pragma unroll
            for (int half = 0; half < 2; half++) {
                const int i = mf * 2 + half;
                #pragma unroll
                for (int nf = 0; nf < 4; nf++) {
                    const int n0 = nBase + wn * 32 + nf * 8 + lr4 * 2;
                    const float d0 = fmaf(-2.0f, acc[mf][nf][half * 2 + 0], csq_s[n0]);
                    const float d1 = fmaf(-2.0f, acc[mf][nf][half * 2 + 1], csq_s[n0 + 1]);
                    if (d0 < rmin[i]) { rmin[i] = d0; ridx[i] = n0; }
                    if (d1 < rmin[i]) { rmin[i] = d1; ridx[i] = n0 + 1; }
                }
            }
    }

    // reduce across the 4 lanes sharing each row (xor 1,2 within quad),
    // then global combine across the 4 n-warps via packed atomicMin.
    #pragma unroll
    for (int i = 0; i < 8; i++) {
        float d  = rmin[i];
        int   ix = ridx[i];
        #pragma unroll
        for (int o = 1; o <= 2; o <<= 1) {
            float od = __shfl_xor_sync(0xffffffffu, d, o);
            int   oi = __shfl_xor_sync(0xffffffffu, ix, o);
            if (od < d || (od == d && oi < ix)) { d = od; ix = oi; }
        }
        if (lr4 == 0) {
            const int row = wm * 64 + (i >> 1) * 16 + (i & 1) * 8 + lq;
            uint32_t db = __float_as_uint(d);
            uint32_t key = (db & 0x80000000u) ? ~db : (db | 0x80000000u);
            unsigned long long pk =
                ((unsigned long long)key << 32) | (uint32_t)ix;
            atomicMin(&minpack[row], pk);
        }
    }
    __syncthreads();

    // cooperative gather: embed[b,t,:] = codebook[t, argmin, :]
    for (int q = tid; q < BM * (D_DIM / 4); q += 256) {
        const int r  = q >> 6;
        const int c  = q & 63;
        const int bi = (int)(uint32_t)(minpack[r] & 0xFFFFFFFFull);
        float4 v = *reinterpret_cast<const float4*>(Cb + (size_t)bi * D_DIM + c * 4);
        *reinterpret_cast<float4*>(
            out + ((size_t)(mBase + r) * T_DIM + t) * D_DIM + c * 4) = v;
    }
    // idxes (float, concatenated after embed in the float32 output)
    if (tid < BM) {
        out[(size_t)B_DIM * T_DIM * D_DIM + (size_t)(mBase + tid) * T_DIM + t]
            = (float)(uint32_t)(minpack[tid] & 0xFFFFFFFFull);
    }
}

// ---------------------------------------------------------------------------
static const uint32_t SMEM_BYTES = 1280u * 4u + 2u * 4u * ARR_H * 4u;  // 40448

extern "C" void kernel_launch(void* const* d_in, const int* in_sizes, int n_in,
                              void* d_out, int out_size) {
    const float* input    = (const float*)d_in[0];
    const float* codebook = (const float*)d_in[1];
    float* out = (float*)d_out;

    cudaFuncSetAttribute(vsq_f16_kernel,
                         cudaFuncAttributeMaxDynamicSharedMemorySize, SMEM_BYTES);

    csq_norm_kernel<<<(T_DIM * K_DIM) / 8, 256>>>(codebook);

    dim3 grid(B_DIM / BM, T_DIM);
    vsq_f16_kernel<<<grid, 256, SMEM_BYTES>>>(input, codebook, out);
}

// round 17
// speedup vs baseline: 1.9087x; 1.0312x over previous
// VSQ fused GEMM+argmin — fp16 hi-only MMA + exact fp32 re-rank of tau-window
#include <cuda_runtime.h>
#include <cuda_fp16.h>
#include <cstdint>

#define B_DIM 2048
#define T_DIM 32
#define K_DIM 1024
#define D_DIM 256

#define BM 128
#define BN 128
#define BK 16
#define TAU 0.25f
#define CAP 8

#define KADDRH(k2, row) ((k2) * 136 + (((k2) >> 2) & 1) * 16 + (row))
#define ARR_H 1104          // > KADDRH(7,135)=1103 (32-bit words)

__device__ float g_csq_norms[T_DIM * K_DIM];

// ---------------------------------------------------------------------------
__global__ void csq_norm_kernel(const float* __restrict__ codebook) {
    int gw   = blockIdx.x * (blockDim.x >> 5) + (threadIdx.x >> 5);
    int lane = threadIdx.x & 31;
    if (gw >= T_DIM * K_DIM) return;
    const float4* p = reinterpret_cast<const float4*>(codebook + (size_t)gw * D_DIM);
    float4 v0 = p[lane];
    float4 v1 = p[lane + 32];
    float s = v0.x*v0.x + v0.y*v0.y + v0.z*v0.z + v0.w*v0.w
            + v1.x*v1.x + v1.y*v1.y + v1.z*v1.z + v1.w*v1.w;
    #pragma unroll
    for (int o = 16; o > 0; o >>= 1) s += __shfl_xor_sync(0xffffffffu, s, o);
    if (lane == 0) g_csq_norms[gw] = s;
}

__device__ __forceinline__ uint32_t pack_h2(float x0, float x1) {
    uint32_t r;
    asm("cvt.rn.f16x2.f32 %0, %1, %2;" : "=r"(r) : "f"(x1), "f"(x0));
    return r;
}

__device__ __forceinline__ void mma_f16(float* c, const uint32_t* a,
                                        const uint32_t* b) {
    asm volatile(
        "mma.sync.aligned.m16n8k16.row.col.f32.f16.f16.f32 "
        "{%0,%1,%2,%3}, {%4,%5,%6,%7}, {%8,%9}, {%0,%1,%2,%3};"
        : "+f"(c[0]), "+f"(c[1]), "+f"(c[2]), "+f"(c[3])
        : "r"(a[0]), "r"(a[1]), "r"(a[2]), "r"(a[3]), "r"(b[0]), "r"(b[1]));
}

__device__ __forceinline__ float decode_key(uint32_t key) {
    uint32_t db = (key & 0x80000000u) ? (key & 0x7FFFFFFFu) : ~key;
    return __uint_as_float(db);
}

// ---------------------------------------------------------------------------
// smem float offsets: csq 0..1023 | minpack(ull) 1024..1279 | cnt 1280..1407 |
// sidx 1408..1535 | list 1536..2559 | bufs 2560.. (2 buf x 2 arrays x ARR_H)
// ---------------------------------------------------------------------------
__global__ __launch_bounds__(256, 2) void vsq_f16_kernel(
    const float* __restrict__ input,
    const float* __restrict__ codebook,
    float* __restrict__ out)
{
    extern __shared__ float sm[];
    float* csq_s = sm;
    unsigned long long* minpack = reinterpret_cast<unsigned long long*>(sm + 1024);
    int* cnt  = reinterpret_cast<int*>(sm + 1280);
    int* sidx = reinterpret_cast<int*>(sm + 1408);
    int* list = reinterpret_cast<int*>(sm + 1536);
    uint32_t* bufs = reinterpret_cast<uint32_t*>(sm + 2560);

    const int t     = blockIdx.y;
    const int mBase = blockIdx.x * BM;
    const int tid   = threadIdx.x;
    const int lane  = tid & 31;
    const int wid   = tid >> 5;
    const int wm    = wid >> 2;
    const int wn    = wid & 3;
    const int lq    = lane >> 2;
    const int lr4   = lane & 3;

    const int lr = tid >> 1;
    const int lh = tid & 1;

    for (int i = tid; i < K_DIM; i += 256) csq_s[i] = g_csq_norms[t * K_DIM + i];
    if (tid < BM) minpack[tid] = 0xFFFFFFFFFFFFFFFFull;
    __syncthreads();

    const size_t ARowStride = (size_t)T_DIM * D_DIM;
    const float* Abase = input    + ((size_t)mBase * T_DIM + t) * D_DIM;
    const float* Cb    = codebook + (size_t)t * K_DIM * D_DIM;

    // per-thread top-2 (d,idx) + 3rd-best d (dropout sentinel), per row i
    float rmin1[8], rmin2[8], rmin3[8];
    int   ridx1[8], ridx2[8];
    #pragma unroll
    for (int i = 0; i < 8; i++) {
        rmin1[i] = 3.4e38f; rmin2[i] = 3.4e38f; rmin3[i] = 3.4e38f;
        ridx1[i] = 0; ridx2[i] = 0;
    }

// stage hi-halves only: va/vb (k = 8*lh..+7, row lr) -> fp16x2 pairs
#define STAGE_HI(AH, BH)                                                  \
    _Pragma("unroll")                                                     \
    for (int e2 = 0; e2 < 4; e2++) {                                      \
        const int ad = KADDRH(4 * lh + e2, lr);                           \
        (AH)[ad] = pack_h2(va[2 * e2], va[2 * e2 + 1]);                   \
        (BH)[ad] = pack_h2(vb[2 * e2], vb[2 * e2 + 1]);                   \
    }

    int buf = 0;
    for (int nTile = 0; nTile < K_DIM / BN; nTile++) {
        const int nBase = nTile * BN;

        float acc[4][4][4];
        #pragma unroll
        for (int mf = 0; mf < 4; mf++)
            #pragma unroll
            for (int nf = 0; nf < 4; nf++)
                #pragma unroll
                for (int r = 0; r < 4; r++) acc[mf][nf][r] = 0.0f;

        const float* Ap = Abase + (size_t)lr * ARowStride + lh * 8;
        const float* Bp = Cb + (size_t)(nBase + lr) * D_DIM + lh * 8;

        float va[8], vb[8];
        #pragma unroll
        for (int i = 0; i < 2; i++) {
            *reinterpret_cast<float4*>(va + i * 4) =
                *reinterpret_cast<const float4*>(Ap + i * 4);
            *reinterpret_cast<float4*>(vb + i * 4) =
                *reinterpret_cast<const float4*>(Bp + i * 4);
        }
        {
            uint32_t* Ah = bufs + buf * 2 * ARR_H;
            uint32_t* Bh = Ah + ARR_H;
            STAGE_HI(Ah, Bh);
        }
        __syncthreads();

        for (int kt = 0; kt < D_DIM / BK; kt++) {
            const bool more = (kt + 1) < (D_DIM / BK);
            if (more) {
                Ap += BK; Bp += BK;
                #pragma unroll
                for (int i = 0; i < 2; i++) {
                    *reinterpret_cast<float4*>(va + i * 4) =
                        *reinterpret_cast<const float4*>(Ap + i * 4);
                    *reinterpret_cast<float4*>(vb + i * 4) =
                        *reinterpret_cast<const float4*>(Bp + i * 4);
                }
            }

            const uint32_t* Ah = bufs + buf * 2 * ARR_H;
            const uint32_t* Bh = Ah + ARR_H;

            uint32_t bh[4][2];
            #pragma unroll
            for (int nf = 0; nf < 4; nf++)
                #pragma unroll
                for (int j = 0; j < 2; j++)
                    bh[nf][j] = Bh[KADDRH(lr4 + j * 4, wn * 32 + nf * 8 + lq)];

            #pragma unroll
            for (int mf = 0; mf < 4; mf++) {
                uint32_t ah[4];
                #pragma unroll
                for (int j = 0; j < 4; j++)
                    ah[j] = Ah[KADDRH(lr4 + (j >> 1) * 4,
                                      wm * 64 + mf * 16 + lq + (j & 1) * 8)];
                #pragma unroll
                for (int nf = 0; nf < 4; nf++)
                    mma_f16(acc[mf][nf], ah, bh[nf]);
            }

            if (more) {
                const int nb = buf ^ 1;
                uint32_t* Ahn = bufs + nb * 2 * ARR_H;
                uint32_t* Bhn = Ahn + ARR_H;
                STAGE_HI(Ahn, Bhn);
                buf = nb;
            }
            __syncthreads();
        }

        // fold approx distances into per-thread top-3 (n ascending per thread)
        #pragma unroll
        for (int mf = 0; mf < 4; mf++)
            #pragma unroll
            for (int half = 0; half < 2; half++) {
                const int i = mf * 2 + half;
                #pragma unroll
                for (int nf = 0; nf < 4; nf++) {
                    const int n0 = nBase + wn * 32 + nf * 8 + lr4 * 2;
                    #pragma unroll
                    for (int e = 0; e < 2; e++) {
                        const int n = n0 + e;
                        const float d =
                            fmaf(-2.0f, acc[mf][nf][half * 2 + e], csq_s[n]);
                        if (d < rmin1[i]) {
                            rmin3[i] = rmin2[i];
                            rmin2[i] = rmin1[i]; ridx2[i] = ridx1[i];
                            rmin1[i] = d;        ridx1[i] = n;
                        } else if (d < rmin2[i]) {
                            rmin3[i] = rmin2[i];
                            rmin2[i] = d; ridx2[i] = n;
                        } else if (d < rmin3[i]) {
                            rmin3[i] = d;
                        }
                    }
                }
            }
    }

    // global approx top-1 per row: quad shfl + packed atomicMin
    #pragma unroll
    for (int i = 0; i < 8; i++) {
        float d  = rmin1[i];
        int   ix = ridx1[i];
        #pragma unroll
        for (int o = 1; o <= 2; o <<= 1) {
            float od = __shfl_xor_sync(0xffffffffu, d, o);
            int   oi = __shfl_xor_sync(0xffffffffu, ix, o);
            if (od < d || (od == d && oi < ix)) { d = od; ix = oi; }
        }
        if (lr4 == 0) {
            const int row = wm * 64 + (i >> 1) * 16 + (i & 1) * 8 + lq;
            uint32_t db = __float_as_uint(d);
            uint32_t key = (db & 0x80000000u) ? ~db : (db | 0x80000000u);
            atomicMin(&minpack[row],
                      ((unsigned long long)key << 32) | (uint32_t)ix);
        }
    }
    __syncthreads();

    if (tid < BM) cnt[tid] = 0;
    __syncthreads();

    // flag phase: collect all candidates with d~ <= M~ + TAU
    #pragma unroll
    for (int i = 0; i < 8; i++) {
        const int row = wm * 64 + (i >> 1) * 16 + (i & 1) * 8 + lq;
        const float thr =
            decode_key((uint32_t)(minpack[row] >> 32)) + TAU;
        if (rmin3[i] <= thr) atomicAdd(&cnt[row], 4096);  // possible dropout
        if (rmin1[i] <= thr) {
            int p = atomicAdd(&cnt[row], 1);
            if ((p & 4095) < CAP) list[row * CAP + (p & 4095)] = ridx1[i];
            else atomicAdd(&cnt[row], 4096);
        }
        if (rmin2[i] <= thr) {
            int p = atomicAdd(&cnt[row], 1);
            if ((p & 4095) < CAP) list[row * CAP + (p & 4095)] = ridx2[i];
            else atomicAdd(&cnt[row], 4096);
        }
    }
    __syncthreads();

    // pass 2: exact fp32 re-rank where the window has >1 member
    {
        const float* xr0 = Abase;  // row r: Abase + r*ARowStride
        for (int rr = 0; rr < 16; rr++) {
            const int row = wid * 16 + rr;
            const int c = cnt[row];
            const int n = c & 4095;
            const bool full = (c >= 4096) || (n > CAP);
            const int approxIdx = (int)(minpack[row] & 0xFFFFFFFFull);
            if (!full && n <= 1) {
                if (lane == 0) sidx[row] = approxIdx;
                continue;
            }
            const float* xr = xr0 + (size_t)row * ARowStride;
            float4 xa = *reinterpret_cast<const float4*>(xr + lane * 8);
            float4 xb = *reinterpret_cast<const float4*>(xr + lane * 8 + 4);
            float bd = 3.4e38f;
            int   bi = 0x7FFFFFFF;
            const int lim = full ? K_DIM : n;
            for (int j = 0; j < lim; j++) {
                const int k = full ? j : list[row * CAP + j];
                const float* cr = Cb + (size_t)k * D_DIM;
                float4 ca = *reinterpret_cast<const float4*>(cr + lane * 8);
                float4 cb = *reinterpret_cast<const float4*>(cr + lane * 8 + 4);
                float s = xa.x * ca.x;
                s = fmaf(xa.y, ca.y, s); s = fmaf(xa.z, ca.z, s);
                s = fmaf(xa.w, ca.w, s); s = fmaf(xb.x, cb.x, s);
                s = fmaf(xb.y, cb.y, s); s = fmaf(xb.z, cb.z, s);
                s = fmaf(xb.w, cb.w, s);
                #pragma unroll
                for (int o = 16; o > 0; o >>= 1)
                    s += __shfl_xor_sync(0xffffffffu, s, o);
                if (lane == 0) {
                    const float d = fmaf(-2.0f, s, csq_s[k]);
                    if (d < bd || (d == bd && k < bi)) { bd = d; bi = k; }
                }
            }
            if (lane == 0) sidx[row] = bi;
        }
    }
    __syncthreads();

    // gather: embed[b,t,:] = codebook[t, sidx[row], :]
    for (int q = tid; q < BM * (D_DIM / 4); q += 256) {
        const int r  = q >> 6;
        const int cc = q & 63;
        const int bi = sidx[r];
        float4 v = *reinterpret_cast<const float4*>(Cb + (size_t)bi * D_DIM + cc * 4);
        *reinterpret_cast<float4*>(
            out + ((size_t)(mBase + r) * T_DIM + t) * D_DIM + cc * 4) = v;
    }
    if (tid < BM) {
        out[(size_t)B_DIM * T_DIM * D_DIM + (size_t)(mBase + tid) * T_DIM + t]
            = (float)sidx[tid];
    }
}

// ---------------------------------------------------------------------------
static const uint32_t SMEM_BYTES = (2560u + 2u * 2u * ARR_H) * 4u;  // 27904

extern "C" void kernel_launch(void* const* d_in, const int* in_sizes, int n_in,
                              void* d_out, int out_size) {
    const float* input    = (const float*)d_in[0];
    const float* codebook = (const float*)d_in[1];
    float* out = (float*)d_out;

    cudaFuncSetAttribute(vsq_f16_kernel,
                         cudaFuncAttributeMaxDynamicSharedMemorySize, SMEM_BYTES);

    csq_norm_kernel<<<(T_DIM * K_DIM) / 8, 256>>>(codebook);

    dim3 grid(B_DIM / BM, T_DIM);
    vsq_f16_kernel<<<grid, 256, SMEM_BYTES>>>(input, codebook, out);
}